// round 9
// baseline (speedup 1.0000x reference)
#include <cuda_runtime.h>
#include <math.h>
#include <stdint.h>

#define TT 512
#define BB 16
#define HH 48
#define SS 4
#define OO 48
#define DD 768
#define NN 9216      /* S*H*O */
#define MTOT 8192    /* B*T */
#define NGROUP 192   /* S*H */

// ---------------- device scratch ----------------
__device__ signed char g_emb8[MTOT * DD];  // 6.3 MB
__device__ signed char g_w8[NN * DD];      // 7.1 MB
__device__ float g_sa[MTOT];
__device__ float g_sb[NN];
__device__ float g_val[MTOT * NGROUP];
__device__ float g_lep[MTOT * HH];
__device__ float g_elep[MTOT * HH];
__device__ float g_alpha[MTOT * HH];   // arbitrary per-t scale
__device__ float g_beta[MTOT * HH];    // arbitrary per-t scale
__device__ float g_partial[MTOT];
__device__ float g_lp[HH];
__device__ float g_log_trans[HH * HH];
__device__ float g_trans_prob[HH * HH];
__device__ float g_emiss_prob[SS * HH * OO];

// ---------------- helpers ----------------
__device__ __forceinline__ uint32_t smem_u32(const void* p) {
    uint32_t a;
    asm("{ .reg .u64 t; cvta.to.shared.u64 t, %1; cvt.u32.u64 %0, t; }" : "=r"(a) : "l"(p));
    return a;
}

__device__ __forceinline__ float fexp(float x) {
    if (x < -87.0f) return 0.0f;
    float t = x * 1.4426950408889634f;
    float n = rintf(t);
    float f = t - n;
    float p = 1.5403530393381609e-4f;
    p = fmaf(p, f, 1.3333558146428443e-3f);
    p = fmaf(p, f, 9.6181291076284772e-3f);
    p = fmaf(p, f, 5.5504108664821580e-2f);
    p = fmaf(p, f, 2.4022650695910072e-1f);
    p = fmaf(p, f, 6.9314718055994531e-1f);
    p = fmaf(p, f, 1.0f);
    int e = (int)n;
    if (e < -126) return 0.0f;
    if (e > 126) e = 126;
    return p * __int_as_float((e + 127) << 23);
}

__device__ __forceinline__ float blockSum256(float v, float* red) {
    int tid = threadIdx.x;
#pragma unroll
    for (int o = 16; o > 0; o >>= 1) v += __shfl_down_sync(0xffffffffu, v, o);
    __syncthreads();
    if ((tid & 31) == 0) red[tid >> 5] = v;
    __syncthreads();
    if (tid < 32) {
        float r = (tid < 8) ? red[tid] : 0.0f;
#pragma unroll
        for (int o = 4; o > 0; o >>= 1) r += __shfl_down_sync(0xffffffffu, r, o);
        if (tid == 0) red[0] = r;
    }
    __syncthreads();
    return red[0];
}

// ---------------- kernel 0: int8 row-quant + prep ----------------
// one warp per row: rows 0..MTOT-1 = emb, MTOT..MTOT+NN-1 = W. last block = prep.
#define QBLOCKS 2176   /* (MTOT + NN) / 8 */
__global__ void __launch_bounds__(256) init_kernel(const float* __restrict__ emb,
                                                   const float* __restrict__ Wm,
                                                   const float* __restrict__ sp,
                                                   const float* __restrict__ ut,
                                                   const float* __restrict__ ue) {
    const unsigned FULL = 0xffffffffu;
    int tid = threadIdx.x;
    if (blockIdx.x < QBLOCKS) {
        int gw = blockIdx.x * 8 + (tid >> 5);
        int lane = tid & 31;
        const float* src;
        signed char* dst;
        float* scl;
        if (gw < MTOT) {
            src = emb + (size_t)gw * DD;
            dst = g_emb8 + (size_t)gw * DD;
            scl = &g_sa[gw];
        } else {
            int r = gw - MTOT;
            src = Wm + (size_t)r * DD;
            dst = g_w8 + (size_t)r * DD;
            scl = &g_sb[r];
        }
        float4 v[6];
        float mx = 0.0f;
#pragma unroll
        for (int j = 0; j < 6; j++) {
            v[j] = ((const float4*)src)[lane + 32 * j];
            mx = fmaxf(mx, fmaxf(fmaxf(fabsf(v[j].x), fabsf(v[j].y)),
                                 fmaxf(fabsf(v[j].z), fabsf(v[j].w))));
        }
#pragma unroll
        for (int o = 16; o > 0; o >>= 1) mx = fmaxf(mx, __shfl_xor_sync(FULL, mx, o));
        float inv = 127.0f / mx;
        if (lane == 0) *scl = mx * (1.0f / 127.0f);
#pragma unroll
        for (int j = 0; j < 6; j++) {
            int q0 = __float2int_rn(v[j].x * inv);
            int q1 = __float2int_rn(v[j].y * inv);
            int q2 = __float2int_rn(v[j].z * inv);
            int q3 = __float2int_rn(v[j].w * inv);
            uint32_t p = (uint32_t)(q0 & 0xff) | ((uint32_t)(q1 & 0xff) << 8) |
                         ((uint32_t)(q2 & 0xff) << 16) | ((uint32_t)(q3 & 0xff) << 24);
            ((uint32_t*)dst)[lane + 32 * j] = p;
        }
        return;
    }
    // ---- prep (last block) ----
    if (tid < HH) {
        const float* row = ut + tid * HH;
        float m = row[0];
#pragma unroll
        for (int j = 1; j < HH; j++) m = fmaxf(m, row[j]);
        float s = 0.0f;
#pragma unroll
        for (int j = 0; j < HH; j++) s += fexp(row[j] - m);
        float ls = logf(s) + m;
#pragma unroll
        for (int j = 0; j < HH; j++) {
            float v = row[j] - ls;
            g_log_trans[tid * HH + j] = v;
            g_trans_prob[tid * HH + j] = fexp(v);
        }
    }
    if (tid < SS * HH) {
        const float* row = ue + tid * OO;
        float m = row[0];
#pragma unroll
        for (int j = 1; j < OO; j++) m = fmaxf(m, row[j]);
        float s = 0.0f;
#pragma unroll
        for (int j = 0; j < OO; j++) s += fexp(row[j] - m);
        float inv = 1.0f / s;
#pragma unroll
        for (int j = 0; j < OO; j++) g_emiss_prob[tid * OO + j] = fexp(row[j] - m) * inv;
    }
    if (tid == 0) {
        float m = sp[0];
        for (int j = 1; j < HH; j++) m = fmaxf(m, sp[j]);
        float s = 0.0f;
        for (int j = 0; j < HH; j++) s += fexp(sp[j] - m);
        float ls = logf(s) + m;
        for (int j = 0; j < HH; j++) g_lp[j] = sp[j] - ls;
    }
}

__global__ void dummy_kernel() {}

// ---------------- kernel 1: fused int8 GEMM (128x96, k128/chunk) + epilogue ----------------
#define STAGE_BYTES 28672            /* A 128x128B + B 96x128B */
#define GEMM_SMEM (4 * STAGE_BYTES)  /* 114688 -> 2 CTAs/SM */
#define NKB 6                         /* 768 / 128 */
__device__ __forceinline__ void cp_async16(uint32_t dst, const void* src) {
    asm volatile("cp.async.cg.shared.global [%0], [%1], 16;" ::
                 "r"(dst), "l"(__cvta_generic_to_global(src)));
}

__global__ void __launch_bounds__(256, 2) mma_fused_kernel(const float* __restrict__ bias,
                                                           const float* __restrict__ obs) {
    extern __shared__ char smem[];
    float* smf = (float*)smem;
    uint32_t sbase = smem_u32(smem);
    const int tid = threadIdx.x;
    const int wid = tid >> 5, lane = tid & 31;
    const int bn = blockIdx.x * 96;
    const int bm = blockIdx.y * 128;
    const int wm = (wid >> 1) * 32;
    const int gsel = wid & 1;
    const int wn = gsel * 48;

    const int sub = lane >> 3, l8 = lane & 7;
    const int a_row_in = (sub & 1) * 8 + l8;
    const int a_kb = (sub >> 1) * 16;       // byte offset within 32B k-step pair
    const int b_row_in = (sub >> 1) * 8 + l8;
    const int b_kb = (sub & 1) * 16;

    uint32_t a_base[2], b_base[3];
    int a_xor[2], b_xor[3];
#pragma unroll
    for (int mi = 0; mi < 2; mi++) {
        int r = wm + mi * 16 + a_row_in;
        a_base[mi] = (uint32_t)(r * 128);
        a_xor[mi] = (r & 7) << 4;
    }
#pragma unroll
    for (int pi = 0; pi < 3; pi++) {
        int r = wn + pi * 16 + b_row_in;
        b_base[pi] = (uint32_t)(r * 128);
        b_xor[pi] = (r & 7) << 4;
    }

    int c[2][6][4];
#pragma unroll
    for (int mi = 0; mi < 2; mi++)
#pragma unroll
        for (int ni = 0; ni < 6; ni++)
#pragma unroll
            for (int q = 0; q < 4; q++) c[mi][ni][q] = 0;

    auto load_tiles = [&](int kb, int stage) {
        uint32_t adst = sbase + (uint32_t)(stage * STAGE_BYTES);
        uint32_t bdst = adst + 16384u;
#pragma unroll
        for (int p = 0; p < 4; p++) {
            int idx = tid + p * 256;
            int r = idx >> 3, cc = idx & 7;
            uint32_t off = (uint32_t)(r * 128 + cc * 16);
            off ^= (uint32_t)((r & 7) << 4);
            cp_async16(adst + off, g_emb8 + (size_t)(bm + r) * DD + kb * 128 + cc * 16);
        }
#pragma unroll
        for (int p = 0; p < 3; p++) {
            int idx = tid + p * 256;
            int r = idx >> 3, cc = idx & 7;
            uint32_t off = (uint32_t)(r * 128 + cc * 16);
            off ^= (uint32_t)((r & 7) << 4);
            cp_async16(bdst + off, g_w8 + (size_t)(bn + r) * DD + kb * 128 + cc * 16);
        }
        asm volatile("cp.async.commit_group;" ::: "memory");
    };

    load_tiles(0, 0);
    load_tiles(1, 1);
    load_tiles(2, 2);

    uint32_t fa[2][2][4];
    uint32_t fb[2][6][2];

    for (int kb = 0; kb < NKB; kb++) {
        if (kb <= NKB - 3)      asm volatile("cp.async.wait_group 2;" ::: "memory");
        else if (kb == NKB - 2) asm volatile("cp.async.wait_group 1;" ::: "memory");
        else                    asm volatile("cp.async.wait_group 0;" ::: "memory");
        __syncthreads();
        if (kb + 3 < NKB) load_tiles(kb + 3, (kb + 3) & 3);

        uint32_t abuf = sbase + (uint32_t)((kb & 3) * STAGE_BYTES);
        uint32_t bbuf = abuf + 16384u;

        auto load_frags = [&](int ks, int pipe) {
#pragma unroll
            for (int mi = 0; mi < 2; mi++) {
                uint32_t addr = abuf + a_base[mi] + (uint32_t)((ks * 32 + a_kb) ^ a_xor[mi]);
                asm volatile("ldmatrix.sync.aligned.m8n8.x4.shared.b16 {%0,%1,%2,%3}, [%4];"
                             : "=r"(fa[pipe][mi][0]), "=r"(fa[pipe][mi][1]),
                               "=r"(fa[pipe][mi][2]), "=r"(fa[pipe][mi][3])
                             : "r"(addr));
            }
#pragma unroll
            for (int pi = 0; pi < 3; pi++) {
                uint32_t addr = bbuf + b_base[pi] + (uint32_t)((ks * 32 + b_kb) ^ b_xor[pi]);
                uint32_t r0, r1, r2, r3;
                asm volatile("ldmatrix.sync.aligned.m8n8.x4.shared.b16 {%0,%1,%2,%3}, [%4];"
                             : "=r"(r0), "=r"(r1), "=r"(r2), "=r"(r3) : "r"(addr));
                fb[pipe][pi * 2][0] = r0; fb[pipe][pi * 2][1] = r1;
                fb[pipe][pi * 2 + 1][0] = r2; fb[pipe][pi * 2 + 1][1] = r3;
            }
        };

        load_frags(0, 0);
#pragma unroll
        for (int ks = 0; ks < 4; ks++) {
            int cur = ks & 1;
            if (ks < 3) load_frags(ks + 1, cur ^ 1);
#pragma unroll
            for (int mi = 0; mi < 2; mi++)
#pragma unroll
                for (int ni = 0; ni < 6; ni++) {
                    asm volatile(
                        "mma.sync.aligned.m16n8k32.row.col.s32.s8.s8.s32 "
                        "{%0,%1,%2,%3}, {%4,%5,%6,%7}, {%8,%9}, {%0,%1,%2,%3};"
                        : "+r"(c[mi][ni][0]), "+r"(c[mi][ni][1]),
                          "+r"(c[mi][ni][2]), "+r"(c[mi][ni][3])
                        : "r"(fa[cur][mi][0]), "r"(fa[cur][mi][1]),
                          "r"(fa[cur][mi][2]), "r"(fa[cur][mi][3]),
                          "r"(fb[cur][ni][0]), "r"(fb[cur][ni][1]));
                }
        }
    }

    // ---------------- fused epilogue ----------------
    const int g0 = blockIdx.x * 2;
    const int s_src = g0 / HH;
    const int EPOFF = 6400;
    __syncthreads();
    for (int i = tid; i < 128 * 24; i += 256) {
        int r = i / 24, c2 = i - r * 24;
        float2 v = *(const float2*)&obs[((size_t)(bm + r) * SS + s_src) * OO + c2 * 2];
        *(float2*)&smf[r * 50 + c2 * 2] = v;
    }
    if (tid < 96) smf[EPOFF + tid] = g_emiss_prob[g0 * 48 + tid];
    __syncthreads();

    const int trow = lane >> 2;
    const int tcol = (lane & 3) * 2;
    const int ggl = g0 + gsel;

    float bx[6], by[6], sbx[6], sby[6];
#pragma unroll
    for (int ni = 0; ni < 6; ni++) {
        float2 bv = *(const float2*)&bias[bn + wn + ni * 8 + tcol];
        bx[ni] = bv.x; by[ni] = bv.y;
        float2 sv = *(const float2*)&g_sb[bn + wn + ni * 8 + tcol];
        sbx[ni] = sv.x; sby[ni] = sv.y;
    }
    float epx[6], epy[6];
#pragma unroll
    for (int ni = 0; ni < 6; ni++) {
        epx[ni] = smf[EPOFF + gsel * 48 + ni * 8 + tcol];
        epy[ni] = smf[EPOFF + gsel * 48 + ni * 8 + tcol + 1];
    }

#pragma unroll
    for (int mi = 0; mi < 2; mi++) {
#pragma unroll
        for (int half = 0; half < 2; half++) {
            int rt = wm + mi * 16 + half * 8 + trow;
            float sar = g_sa[bm + rt];
            float vx[6], vy[6];
            float mx = -3.0e38f;
#pragma unroll
            for (int ni = 0; ni < 6; ni++) {
                vx[ni] = (float)c[mi][ni][half * 2] * (sar * sbx[ni]) + bx[ni];
                vy[ni] = (float)c[mi][ni][half * 2 + 1] * (sar * sby[ni]) + by[ni];
                mx = fmaxf(mx, fmaxf(vx[ni], vy[ni]));
            }
            mx = fmaxf(mx, __shfl_xor_sync(0xffffffffu, mx, 1));
            mx = fmaxf(mx, __shfl_xor_sync(0xffffffffu, mx, 2));
            float den = 0.0f, dot = 0.0f, eo = 0.0f;
            const float* obr = &smf[rt * 50];
#pragma unroll
            for (int ni = 0; ni < 6; ni++) {
                float obx = obr[ni * 8 + tcol];
                float oby = obr[ni * 8 + tcol + 1];
                float ex = fexp(vx[ni] - mx);
                float ey = fexp(vy[ni] - mx);
                den += ex + ey;
                dot = fmaf(ex, obx, dot);
                dot = fmaf(ey, oby, dot);
                eo = fmaf(epx[ni], obx, eo);
                eo = fmaf(epy[ni], oby, eo);
            }
#pragma unroll
            for (int m = 1; m <= 2; m <<= 1) {
                den += __shfl_xor_sync(0xffffffffu, den, m);
                dot += __shfl_xor_sync(0xffffffffu, dot, m);
                eo  += __shfl_xor_sync(0xffffffffu, eo, m);
            }
            if ((lane & 3) == 0) {
                float val = 0.5f * eo + 0.5f * (dot / den);
                g_val[(size_t)(bm + rt) * NGROUP + ggl] = val;
            }
        }
    }
}

// ---------------- kernel 1b: combine 4 sources -> elep/lep ----------------
__global__ void __launch_bounds__(256) combine_kernel() {
    int idx = blockIdx.x * 256 + threadIdx.x;
    if (idx >= MTOT * HH) return;
    int bt = idx / HH, h = idx - bt * HH;
    const float* v = g_val + (size_t)bt * NGROUP + h;
    float p = v[0] * v[48] * v[96] * v[144];
    g_elep[idx] = p;
    g_lep[idx] = logf(p);
}

// ---------------- kernel 3: barrier-free single-warp scans (round-7 best) ----------------
__global__ void __launch_bounds__(32) scan_kernel() {
    const unsigned FULL = 0xffffffffu;
    int l = threadIdx.x;
    int b = blockIdx.x & 15;
    bool fwd = blockIdx.x < 16;
    bool two = l < 16;
    const float* E = g_elep + (size_t)(b * TT) * HH;

    float T0[HH], T1[HH];
    if (fwd) {
#pragma unroll
        for (int i = 0; i < HH; i++) {
            T0[i] = g_trans_prob[i * HH + l];
            T1[i] = two ? g_trans_prob[i * HH + 32 + l] : 0.0f;
        }
        float a0 = fexp(g_lp[l]) * E[l];
        float a1 = two ? fexp(g_lp[32 + l]) * E[32 + l] : 0.0f;
        g_alpha[(size_t)(b * TT) * HH + l] = a0;
        if (two) g_alpha[(size_t)(b * TT) * HH + 32 + l] = a1;
        float eA0 = E[HH + l];
        float eA1 = two ? E[HH + 32 + l] : 0.0f;
        float eB0 = E[2 * HH + l];
        float eB1 = two ? E[2 * HH + 32 + l] : 0.0f;
        for (int t = 1; t < TT; t++) {
            float el0 = eA0, el1 = eA1;
            eA0 = eB0; eA1 = eB1;
            if (t + 2 < TT) {
                eB0 = E[(t + 2) * HH + l];
                eB1 = two ? E[(t + 2) * HH + 32 + l] : 0.0f;
            }
            float p0 = 0, p1 = 0, p2 = 0, p3 = 0;
            float q0 = 0, q1 = 0, q2 = 0, q3 = 0;
#pragma unroll
            for (int i = 0; i < 32; i += 4) {
                float v0 = __shfl_sync(FULL, a0, i);
                float v1 = __shfl_sync(FULL, a0, i + 1);
                float v2 = __shfl_sync(FULL, a0, i + 2);
                float v3 = __shfl_sync(FULL, a0, i + 3);
                p0 = fmaf(v0, T0[i], p0);     q0 = fmaf(v0, T1[i], q0);
                p1 = fmaf(v1, T0[i + 1], p1); q1 = fmaf(v1, T1[i + 1], q1);
                p2 = fmaf(v2, T0[i + 2], p2); q2 = fmaf(v2, T1[i + 2], q2);
                p3 = fmaf(v3, T0[i + 3], p3); q3 = fmaf(v3, T1[i + 3], q3);
            }
#pragma unroll
            for (int i = 0; i < 16; i += 4) {
                float v0 = __shfl_sync(FULL, a1, i);
                float v1 = __shfl_sync(FULL, a1, i + 1);
                float v2 = __shfl_sync(FULL, a1, i + 2);
                float v3 = __shfl_sync(FULL, a1, i + 3);
                p0 = fmaf(v0, T0[32 + i], p0);     q0 = fmaf(v0, T1[32 + i], q0);
                p1 = fmaf(v1, T0[32 + i + 1], p1); q1 = fmaf(v1, T1[32 + i + 1], q1);
                p2 = fmaf(v2, T0[32 + i + 2], p2); q2 = fmaf(v2, T1[32 + i + 2], q2);
                p3 = fmaf(v3, T0[32 + i + 3], p3); q3 = fmaf(v3, T1[32 + i + 3], q3);
            }
            a0 = (p0 + p1 + p2 + p3) * el0;
            a1 = (q0 + q1 + q2 + q3) * el1;
            g_alpha[(size_t)(b * TT + t) * HH + l] = a0;
            if (two) g_alpha[(size_t)(b * TT + t) * HH + 32 + l] = a1;
            if ((t & 1) == 0) {
                float s = a0 + a1;
#pragma unroll
                for (int o = 16; o > 0; o >>= 1) s += __shfl_xor_sync(FULL, s, o);
                float inv = 1.0f / s;
                a0 *= inv; a1 *= inv;
            }
        }
    } else {
#pragma unroll
        for (int j = 0; j < HH; j++) {
            T0[j] = g_trans_prob[l * HH + j];
            T1[j] = two ? g_trans_prob[(32 + l) * HH + j] : 0.0f;
        }
        float b0 = 1.0f;
        float b1 = two ? 1.0f : 0.0f;
        g_beta[(size_t)(b * TT + TT - 1) * HH + l] = 1.0f;
        if (two) g_beta[(size_t)(b * TT + TT - 1) * HH + 32 + l] = 1.0f;
        float eA0 = E[(TT - 2) * HH + l];
        float eA1 = two ? E[(TT - 2) * HH + 32 + l] : 0.0f;
        float eB0 = E[(TT - 3) * HH + l];
        float eB1 = two ? E[(TT - 3) * HH + 32 + l] : 0.0f;
        for (int t = TT - 2; t >= 0; t--) {
            float el0 = eA0, el1 = eA1;
            eA0 = eB0; eA1 = eB1;
            if (t - 2 >= 0) {
                eB0 = E[(t - 2) * HH + l];
                eB1 = two ? E[(t - 2) * HH + 32 + l] : 0.0f;
            }
            float u0 = el0 * b0;
            float u1 = el1 * b1;
            float p0 = 0, p1 = 0, p2 = 0, p3 = 0;
            float q0 = 0, q1 = 0, q2 = 0, q3 = 0;
#pragma unroll
            for (int j = 0; j < 32; j += 4) {
                float v0 = __shfl_sync(FULL, u0, j);
                float v1 = __shfl_sync(FULL, u0, j + 1);
                float v2 = __shfl_sync(FULL, u0, j + 2);
                float v3 = __shfl_sync(FULL, u0, j + 3);
                p0 = fmaf(v0, T0[j], p0);     q0 = fmaf(v0, T1[j], q0);
                p1 = fmaf(v1, T0[j + 1], p1); q1 = fmaf(v1, T1[j + 1], q1);
                p2 = fmaf(v2, T0[j + 2], p2); q2 = fmaf(v2, T1[j + 2], q2);
                p3 = fmaf(v3, T0[j + 3], p3); q3 = fmaf(v3, T1[j + 3], q3);
            }
#pragma unroll
            for (int j = 0; j < 16; j += 4) {
                float v0 = __shfl_sync(FULL, u1, j);
                float v1 = __shfl_sync(FULL, u1, j + 1);
                float v2 = __shfl_sync(FULL, u1, j + 2);
                float v3 = __shfl_sync(FULL, u1, j + 3);
                p0 = fmaf(v0, T0[32 + j], p0);     q0 = fmaf(v0, T1[32 + j], q0);
                p1 = fmaf(v1, T0[32 + j + 1], p1); q1 = fmaf(v1, T1[32 + j + 1], q1);
                p2 = fmaf(v2, T0[32 + j + 2], p2); q2 = fmaf(v2, T1[32 + j + 2], q2);
                p3 = fmaf(v3, T0[32 + j + 3], p3); q3 = fmaf(v3, T1[32 + j + 3], q3);
            }
            b0 = p0 + p1 + p2 + p3;
            b1 = q0 + q1 + q2 + q3;
            g_beta[(size_t)(b * TT + t) * HH + l] = b0;
            if (two) g_beta[(size_t)(b * TT + t) * HH + 32 + l] = b1;
            if ((t & 1) == 0) {
                float s = b0 + b1;
#pragma unroll
                for (int o = 16; o > 0; o >>= 1) s += __shfl_xor_sync(FULL, s, o);
                float inv = 1.0f / s;
                b0 *= inv; b1 *= inv;
            }
        }
    }
}

// ---------------- kernel 4: per-(b,t) gamma / prior / xi terms ----------------
__global__ void __launch_bounds__(256) final_kernel(const int* __restrict__ seq) {
    __shared__ float lt[HH * HH];
    __shared__ float tp[HH * HH];
    __shared__ float sA[HH], sU[HH], sG[HH], sL[HH];
    __shared__ float red[32];
    int tid = threadIdx.x;
    int bt = blockIdx.x;
    int b = bt >> 9;
    int t = bt & (TT - 1);
    int len = seq[b];

    if (t >= len) {
        if (tid == 0) g_partial[bt] = 0.0f;
        return;
    }
    bool do_xi = (t >= 1);

    for (int i = tid; i < HH * HH; i += 256) {
        lt[i] = g_log_trans[i];
        tp[i] = g_trans_prob[i];
    }
    if (tid < HH) {
        int tb = (t + TT - len) & (TT - 1);
        float br = g_beta[(size_t)(b * TT + tb) * HH + tid];
        float at = g_alpha[(size_t)(b * TT + t) * HH + tid];
        float lpv = g_lep[(size_t)(b * TT + t) * HH + tid];
        float el = g_elep[(size_t)(b * TT + t) * HH + tid];
        sG[tid] = at * br;
        sU[tid] = el * br;
        sL[tid] = lpv;
        sA[tid] = (t > 0) ? g_alpha[(size_t)(b * TT + t - 1) * HH + tid] : 0.0f;
    }
    __syncthreads();

    float e = (tid < HH) ? sG[tid] : 0.0f;
    float Z = blockSum256(e, red);
    float E = blockSum256(e * ((tid < HH) ? sL[tid] : 0.0f), red);
    float total = E / Z;
    if (t == 0) {
        float P = blockSum256(e * ((tid < HH) ? g_lp[tid] : 0.0f), red);
        total += P / Z;
    }

    if (do_xi) {
        float z = 0.0f, w = 0.0f;
        for (int idx = tid; idx < HH * HH; idx += 256) {
            int i = idx / HH, j = idx - i * HH;
            float val = tp[idx] * sA[i] * sU[j];
            z += val;
            w = fmaf(val, lt[idx], w);
        }
        float Z2 = blockSum256(z, red);
        float W2 = blockSum256(w, red);
        total += W2 / Z2;
    }
    if (tid == 0) g_partial[bt] = total;
}

// ---------------- kernel 5: deterministic final reduction ----------------
__global__ void __launch_bounds__(256) reduce_kernel(float* __restrict__ out) {
    __shared__ float red[256];
    int tid = threadIdx.x;
    float s = 0.0f;
    for (int i = tid; i < MTOT; i += 256) s += g_partial[i];
    red[tid] = s;
    __syncthreads();
    for (int off = 128; off > 0; off >>= 1) {
        if (tid < off) red[tid] += red[tid + off];
        __syncthreads();
    }
    if (tid == 0) out[0] = red[0] * (1.0f / (float)BB);
}

// ---------------- launch ----------------
extern "C" void kernel_launch(void* const* d_in, const int* in_sizes, int n_in,
                              void* d_out, int out_size) {
    const float* emb  = (const float*)d_in[0];
    const float* obs  = (const float*)d_in[1];
    const float* sp   = (const float*)d_in[2];
    const float* ut   = (const float*)d_in[3];
    const float* ue   = (const float*)d_in[4];
    const float* Wm   = (const float*)d_in[5];
    const float* bias = (const float*)d_in[6];
    const int*   seq  = (const int*)d_in[7];
    float* out = (float*)d_out;

    cudaFuncSetAttribute(mma_fused_kernel, cudaFuncAttributeMaxDynamicSharedMemorySize, GEMM_SMEM);

    init_kernel<<<QBLOCKS + 1, 256>>>(emb, Wm, sp, ut, ue);       // launch 1
    dummy_kernel<<<1, 32>>>();                                    // launch 2
    dummy_kernel<<<1, 32>>>();                                    // launch 3

    dim3 ggrid(NN / 96, MTOT / 128);
    mma_fused_kernel<<<ggrid, 256, GEMM_SMEM>>>(bias, obs);       // launch 4 <- ncu window
    combine_kernel<<<(MTOT * HH + 255) / 256, 256>>>();           // launch 5

    scan_kernel<<<32, 32>>>();                                    // launch 6
    final_kernel<<<MTOT, 256>>>(seq);                             // launch 7
    reduce_kernel<<<1, 256>>>(out);                               // launch 8
}

// round 10
// speedup vs baseline: 1.5648x; 1.5648x over previous
#include <cuda_runtime.h>
#include <cuda_bf16.h>
#include <math.h>
#include <stdint.h>

#define TT 512
#define BB 16
#define HH 48
#define SS 4
#define OO 48
#define DD 768
#define NN 9216      /* S*H*O */
#define MTOT 8192    /* B*T */
#define NGROUP 192   /* S*H */

// ---------------- device scratch ----------------
__device__ __nv_bfloat16 g_emb16[MTOT * DD];
__device__ __nv_bfloat16 g_w16[NN * DD];
__device__ float g_val[MTOT * NGROUP];
__device__ float g_lep[MTOT * HH];
__device__ float g_elep[MTOT * HH];
__device__ float g_alpha[MTOT * HH];   // arbitrary per-t scale
__device__ float g_beta[MTOT * HH];    // arbitrary per-t scale
__device__ float g_partial[MTOT];
__device__ float g_lp[HH];
__device__ float g_log_trans[HH * HH];
__device__ float g_trans_prob[HH * HH];
__device__ float g_emiss_prob[SS * HH * OO];

// ---------------- helpers ----------------
__device__ __forceinline__ uint32_t smem_u32(const void* p) {
    uint32_t a;
    asm("{ .reg .u64 t; cvta.to.shared.u64 t, %1; cvt.u32.u64 %0, t; }" : "=r"(a) : "l"(p));
    return a;
}

__device__ __forceinline__ float fexp(float x) {
    if (x < -87.0f) return 0.0f;
    float t = x * 1.4426950408889634f;
    float n = rintf(t);
    float f = t - n;
    float p = 1.5403530393381609e-4f;
    p = fmaf(p, f, 1.3333558146428443e-3f);
    p = fmaf(p, f, 9.6181291076284772e-3f);
    p = fmaf(p, f, 5.5504108664821580e-2f);
    p = fmaf(p, f, 2.4022650695910072e-1f);
    p = fmaf(p, f, 6.9314718055994531e-1f);
    p = fmaf(p, f, 1.0f);
    int e = (int)n;
    if (e < -126) return 0.0f;
    if (e > 126) e = 126;
    return p * __int_as_float((e + 127) << 23);
}

__device__ __forceinline__ float blockSum256(float v, float* red) {
    int tid = threadIdx.x;
#pragma unroll
    for (int o = 16; o > 0; o >>= 1) v += __shfl_down_sync(0xffffffffu, v, o);
    __syncthreads();
    if ((tid & 31) == 0) red[tid >> 5] = v;
    __syncthreads();
    if (tid < 32) {
        float r = (tid < 8) ? red[tid] : 0.0f;
#pragma unroll
        for (int o = 4; o > 0; o >>= 1) r += __shfl_down_sync(0xffffffffu, r, o);
        if (tid == 0) red[0] = r;
    }
    __syncthreads();
    return red[0];
}

// ---------------- kernel 0: convert + prep merged ----------------
#define CONV_BLOCKS 13056   /* (MTOT*DD/4 + NN*DD/4) / 256 exactly */
__global__ void __launch_bounds__(256) init_kernel(const float* __restrict__ emb,
                                                   const float* __restrict__ Wm,
                                                   const float* __restrict__ sp,
                                                   const float* __restrict__ ut,
                                                   const float* __restrict__ ue) {
    const int nA = MTOT * DD / 4;
    const int nW = NN * DD / 4;
    int blk = blockIdx.x;
    int tid = threadIdx.x;
    if (blk < CONV_BLOCKS) {
        int i = blk * 256 + tid;
        if (i < nA) {
            float4 v = ((const float4*)emb)[i];
            __nv_bfloat162 lo = __floats2bfloat162_rn(v.x, v.y);
            __nv_bfloat162 hi = __floats2bfloat162_rn(v.z, v.w);
            ((__nv_bfloat162*)g_emb16)[i * 2] = lo;
            ((__nv_bfloat162*)g_emb16)[i * 2 + 1] = hi;
        } else if (i < nA + nW) {
            int j = i - nA;
            float4 v = ((const float4*)Wm)[j];
            __nv_bfloat162 lo = __floats2bfloat162_rn(v.x, v.y);
            __nv_bfloat162 hi = __floats2bfloat162_rn(v.z, v.w);
            ((__nv_bfloat162*)g_w16)[j * 2] = lo;
            ((__nv_bfloat162*)g_w16)[j * 2 + 1] = hi;
        }
        return;
    }
    if (tid < HH) {
        const float* row = ut + tid * HH;
        float m = row[0];
#pragma unroll
        for (int j = 1; j < HH; j++) m = fmaxf(m, row[j]);
        float s = 0.0f;
#pragma unroll
        for (int j = 0; j < HH; j++) s += fexp(row[j] - m);
        float ls = logf(s) + m;
#pragma unroll
        for (int j = 0; j < HH; j++) {
            float v = row[j] - ls;
            g_log_trans[tid * HH + j] = v;
            g_trans_prob[tid * HH + j] = fexp(v);
        }
    }
    if (tid < SS * HH) {
        const float* row = ue + tid * OO;
        float m = row[0];
#pragma unroll
        for (int j = 1; j < OO; j++) m = fmaxf(m, row[j]);
        float s = 0.0f;
#pragma unroll
        for (int j = 0; j < OO; j++) s += fexp(row[j] - m);
        float inv = 1.0f / s;
#pragma unroll
        for (int j = 0; j < OO; j++) g_emiss_prob[tid * OO + j] = fexp(row[j] - m) * inv;
    }
    if (tid == 0) {
        float m = sp[0];
        for (int j = 1; j < HH; j++) m = fmaxf(m, sp[j]);
        float s = 0.0f;
        for (int j = 0; j < HH; j++) s += fexp(sp[j] - m);
        float ls = logf(s) + m;
        for (int j = 0; j < HH; j++) g_lp[j] = sp[j] - ls;
    }
}

// ---------------- kernel 1: fused bf16 GEMM (128x96, 256 thr, 4-stage, frag pipeline) ----------------
#define STAGE_BYTES 28672            /* A 16384 + B 12288 */
#define GEMM_SMEM (4 * STAGE_BYTES)  /* 114688 -> 2 CTAs/SM */
__device__ __forceinline__ void cp_async16(uint32_t dst, const void* src) {
    asm volatile("cp.async.cg.shared.global [%0], [%1], 16;" ::
                 "r"(dst), "l"(__cvta_generic_to_global(src)));
}

__global__ void __launch_bounds__(256, 2) mma_fused_kernel(const float* __restrict__ bias,
                                                           const float* __restrict__ obs) {
    extern __shared__ char smem[];
    float* smf = (float*)smem;
    uint32_t sbase = smem_u32(smem);
    const int tid = threadIdx.x;
    const int wid = tid >> 5, lane = tid & 31;
    const int bn = blockIdx.x * 96;
    const int bm = blockIdx.y * 128;
    const int wm = (wid >> 1) * 32;
    const int gsel = wid & 1;
    const int wn = gsel * 48;

    const int sub = lane >> 3, l8 = lane & 7;
    const int a_row_in = (sub & 1) * 8 + l8;
    const int a_kb = (sub >> 1) * 16;
    const int b_row_in = (sub >> 1) * 8 + l8;
    const int b_kb = (sub & 1) * 16;

    uint32_t a_base[2], b_base[3];
    int a_xor[2], b_xor[3];
#pragma unroll
    for (int mi = 0; mi < 2; mi++) {
        int r = wm + mi * 16 + a_row_in;
        a_base[mi] = (uint32_t)(r * 128);
        a_xor[mi] = (r & 7) << 4;
    }
#pragma unroll
    for (int pi = 0; pi < 3; pi++) {
        int r = wn + pi * 16 + b_row_in;
        b_base[pi] = (uint32_t)(r * 128);
        b_xor[pi] = (r & 7) << 4;
    }

    float c[2][6][4];
#pragma unroll
    for (int mi = 0; mi < 2; mi++)
#pragma unroll
        for (int ni = 0; ni < 6; ni++)
#pragma unroll
            for (int q = 0; q < 4; q++) c[mi][ni][q] = 0.0f;

    auto load_tiles = [&](int kb, int stage) {
        uint32_t adst = sbase + (uint32_t)(stage * STAGE_BYTES);
        uint32_t bdst = adst + 16384u;
#pragma unroll
        for (int p = 0; p < 4; p++) {
            int idx = tid + p * 256;
            int r = idx >> 3, cc = idx & 7;
            uint32_t off = (uint32_t)(r * 128 + cc * 16);
            off ^= (uint32_t)((r & 7) << 4);
            cp_async16(adst + off, g_emb16 + (size_t)(bm + r) * DD + kb * 64 + cc * 8);
        }
#pragma unroll
        for (int p = 0; p < 3; p++) {
            int idx = tid + p * 256;
            int r = idx >> 3, cc = idx & 7;
            uint32_t off = (uint32_t)(r * 128 + cc * 16);
            off ^= (uint32_t)((r & 7) << 4);
            cp_async16(bdst + off, g_w16 + (size_t)(bn + r) * DD + kb * 64 + cc * 8);
        }
        asm volatile("cp.async.commit_group;" ::: "memory");
    };

    load_tiles(0, 0);
    load_tiles(1, 1);
    load_tiles(2, 2);

    uint32_t fa[2][2][4];
    uint32_t fb[2][6][2];

    for (int kb = 0; kb < 12; kb++) {
        if (kb <= 9)       asm volatile("cp.async.wait_group 2;" ::: "memory");
        else if (kb == 10) asm volatile("cp.async.wait_group 1;" ::: "memory");
        else               asm volatile("cp.async.wait_group 0;" ::: "memory");
        __syncthreads();
        if (kb + 3 < 12) load_tiles(kb + 3, (kb + 3) & 3);

        uint32_t abuf = sbase + (uint32_t)((kb & 3) * STAGE_BYTES);
        uint32_t bbuf = abuf + 16384u;

        auto load_frags = [&](int ks, int pipe) {
#pragma unroll
            for (int mi = 0; mi < 2; mi++) {
                uint32_t addr = abuf + a_base[mi] + (uint32_t)((ks * 32 + a_kb) ^ a_xor[mi]);
                asm volatile("ldmatrix.sync.aligned.m8n8.x4.shared.b16 {%0,%1,%2,%3}, [%4];"
                             : "=r"(fa[pipe][mi][0]), "=r"(fa[pipe][mi][1]),
                               "=r"(fa[pipe][mi][2]), "=r"(fa[pipe][mi][3])
                             : "r"(addr));
            }
#pragma unroll
            for (int pi = 0; pi < 3; pi++) {
                uint32_t addr = bbuf + b_base[pi] + (uint32_t)((ks * 32 + b_kb) ^ b_xor[pi]);
                uint32_t r0, r1, r2, r3;
                asm volatile("ldmatrix.sync.aligned.m8n8.x4.shared.b16 {%0,%1,%2,%3}, [%4];"
                             : "=r"(r0), "=r"(r1), "=r"(r2), "=r"(r3) : "r"(addr));
                fb[pipe][pi * 2][0] = r0; fb[pipe][pi * 2][1] = r1;
                fb[pipe][pi * 2 + 1][0] = r2; fb[pipe][pi * 2 + 1][1] = r3;
            }
        };

        load_frags(0, 0);
#pragma unroll
        for (int ks = 0; ks < 4; ks++) {
            int cur = ks & 1;
            if (ks < 3) load_frags(ks + 1, cur ^ 1);
#pragma unroll
            for (int mi = 0; mi < 2; mi++)
#pragma unroll
                for (int ni = 0; ni < 6; ni++) {
                    asm volatile(
                        "mma.sync.aligned.m16n8k16.row.col.f32.bf16.bf16.f32 "
                        "{%0,%1,%2,%3}, {%4,%5,%6,%7}, {%8,%9}, {%0,%1,%2,%3};"
                        : "+f"(c[mi][ni][0]), "+f"(c[mi][ni][1]),
                          "+f"(c[mi][ni][2]), "+f"(c[mi][ni][3])
                        : "r"(fa[cur][mi][0]), "r"(fa[cur][mi][1]),
                          "r"(fa[cur][mi][2]), "r"(fa[cur][mi][3]),
                          "r"(fb[cur][ni][0]), "r"(fb[cur][ni][1]));
                }
        }
    }

    // ---------------- fused epilogue ----------------
    const int g0 = blockIdx.x * 2;
    const int s_src = g0 / HH;
    const int EPOFF = 6400;
    __syncthreads();
    for (int i = tid; i < 128 * 24; i += 256) {
        int r = i / 24, c2 = i - r * 24;
        float2 v = *(const float2*)&obs[((size_t)(bm + r) * SS + s_src) * OO + c2 * 2];
        *(float2*)&smf[r * 50 + c2 * 2] = v;
    }
    if (tid < 96) smf[EPOFF + tid] = g_emiss_prob[g0 * 48 + tid];
    __syncthreads();

    const int trow = lane >> 2;
    const int tcol = (lane & 3) * 2;
    const int ggl = g0 + gsel;

    float bx[6], by[6];
#pragma unroll
    for (int ni = 0; ni < 6; ni++) {
        float2 bv = *(const float2*)&bias[bn + wn + ni * 8 + tcol];
        bx[ni] = bv.x; by[ni] = bv.y;
    }
    float epx[6], epy[6];
#pragma unroll
    for (int ni = 0; ni < 6; ni++) {
        epx[ni] = smf[EPOFF + gsel * 48 + ni * 8 + tcol];
        epy[ni] = smf[EPOFF + gsel * 48 + ni * 8 + tcol + 1];
    }

#pragma unroll
    for (int mi = 0; mi < 2; mi++) {
#pragma unroll
        for (int half = 0; half < 2; half++) {
            int rt = wm + mi * 16 + half * 8 + trow;
            float vx[6], vy[6];
            float mx = -3.0e38f;
#pragma unroll
            for (int ni = 0; ni < 6; ni++) {
                vx[ni] = c[mi][ni][half * 2] + bx[ni];
                vy[ni] = c[mi][ni][half * 2 + 1] + by[ni];
                mx = fmaxf(mx, fmaxf(vx[ni], vy[ni]));
            }
            mx = fmaxf(mx, __shfl_xor_sync(0xffffffffu, mx, 1));
            mx = fmaxf(mx, __shfl_xor_sync(0xffffffffu, mx, 2));
            float den = 0.0f, dot = 0.0f, eo = 0.0f;
            const float* obr = &smf[rt * 50];
#pragma unroll
            for (int ni = 0; ni < 6; ni++) {
                float obx = obr[ni * 8 + tcol];
                float oby = obr[ni * 8 + tcol + 1];
                float ex = fexp(vx[ni] - mx);
                float ey = fexp(vy[ni] - mx);
                den += ex + ey;
                dot = fmaf(ex, obx, dot);
                dot = fmaf(ey, oby, dot);
                eo = fmaf(epx[ni], obx, eo);
                eo = fmaf(epy[ni], oby, eo);
            }
#pragma unroll
            for (int m = 1; m <= 2; m <<= 1) {
                den += __shfl_xor_sync(0xffffffffu, den, m);
                dot += __shfl_xor_sync(0xffffffffu, dot, m);
                eo  += __shfl_xor_sync(0xffffffffu, eo, m);
            }
            if ((lane & 3) == 0) {
                float val = 0.5f * eo + 0.5f * (dot / den);
                g_val[(size_t)(bm + rt) * NGROUP + ggl] = val;
            }
        }
    }
}

// ---------------- kernel 1b: combine 4 sources -> elep/lep ----------------
__global__ void __launch_bounds__(256) combine_kernel() {
    int idx = blockIdx.x * 256 + threadIdx.x;
    if (idx >= MTOT * HH) return;
    int bt = idx / HH, h = idx - bt * HH;
    const float* v = g_val + (size_t)bt * NGROUP + h;
    float p = v[0] * v[48] * v[96] * v[144];
    g_elep[idx] = p;
    g_lep[idx] = logf(p);
}

// ---------------- kernel 3: single-warp scans, smem broadcast, syncwarp only ----------------
// block = 1 warp = one (b, dir). lane l owns states {l} and {32+l | l<16}.
// state vector double-buffered in smem; reads are LDS.128 broadcasts.
__global__ void __launch_bounds__(32) scan_kernel() {
    __shared__ __align__(16) float buf[2][HH];
    const unsigned FULL = 0xffffffffu;
    int l = threadIdx.x;
    int b = blockIdx.x & 15;
    bool fwd = blockIdx.x < 16;
    bool two = l < 16;
    const float* E = g_elep + (size_t)(b * TT) * HH;

    float T0[HH], T1[HH];
    if (fwd) {
        // columns: T0[i] = trans[i][l], T1[i] = trans[i][32+l]
#pragma unroll
        for (int i = 0; i < HH; i++) {
            T0[i] = g_trans_prob[i * HH + l];
            T1[i] = two ? g_trans_prob[i * HH + 32 + l] : 0.0f;
        }
        float a0 = fexp(g_lp[l]) * E[l];
        float a1 = two ? fexp(g_lp[32 + l]) * E[32 + l] : 0.0f;
        g_alpha[(size_t)(b * TT) * HH + l] = a0;
        if (two) g_alpha[(size_t)(b * TT) * HH + 32 + l] = a1;
        buf[0][l] = a0;
        if (two) buf[0][32 + l] = a1;
        __syncwarp(FULL);
        float eA0 = E[HH + l];
        float eA1 = two ? E[HH + 32 + l] : 0.0f;
        float eB0 = E[2 * HH + l];
        float eB1 = two ? E[2 * HH + 32 + l] : 0.0f;
        for (int t = 1; t < TT; t++) {
            float el0 = eA0, el1 = eA1;
            eA0 = eB0; eA1 = eB1;
            if (t + 2 < TT) {
                eB0 = E[(t + 2) * HH + l];
                eB1 = two ? E[(t + 2) * HH + 32 + l] : 0.0f;
            }
            const float4* v4 = (const float4*)buf[(t - 1) & 1];
            float p0 = 0, p1 = 0, q0 = 0, q1 = 0;
#pragma unroll
            for (int i = 0; i < 12; i++) {
                float4 v = v4[i];
                p0 = fmaf(v.x, T0[4 * i + 0], p0); q0 = fmaf(v.x, T1[4 * i + 0], q0);
                p1 = fmaf(v.y, T0[4 * i + 1], p1); q1 = fmaf(v.y, T1[4 * i + 1], q1);
                p0 = fmaf(v.z, T0[4 * i + 2], p0); q0 = fmaf(v.z, T1[4 * i + 2], q0);
                p1 = fmaf(v.w, T0[4 * i + 3], p1); q1 = fmaf(v.w, T1[4 * i + 3], q1);
            }
            float a0n = (p0 + p1) * el0;
            float a1n = (q0 + q1) * el1;   // el1 = 0 for l >= 16
            g_alpha[(size_t)(b * TT + t) * HH + l] = a0n;
            if (two) g_alpha[(size_t)(b * TT + t) * HH + 32 + l] = a1n;
            if ((t & 1) == 0) {            // underflow guard every 2 steps
                float s = a0n + a1n;
#pragma unroll
                for (int o = 16; o > 0; o >>= 1) s += __shfl_xor_sync(FULL, s, o);
                float inv = 1.0f / s;
                a0n *= inv; a1n *= inv;
            }
            buf[t & 1][l] = a0n;
            if (two) buf[t & 1][32 + l] = a1n;
            __syncwarp(FULL);
        }
    } else {
        // rows: T0[j] = trans[l][j], T1[j] = trans[32+l][j]
#pragma unroll
        for (int j = 0; j < HH; j++) {
            T0[j] = g_trans_prob[l * HH + j];
            T1[j] = two ? g_trans_prob[(32 + l) * HH + j] : 0.0f;
        }
        float b0 = 1.0f;
        float b1 = two ? 1.0f : 0.0f;
        g_beta[(size_t)(b * TT + TT - 1) * HH + l] = 1.0f;
        if (two) g_beta[(size_t)(b * TT + TT - 1) * HH + 32 + l] = 1.0f;
        float eA0 = E[(TT - 2) * HH + l];
        float eA1 = two ? E[(TT - 2) * HH + 32 + l] : 0.0f;
        float eB0 = E[(TT - 3) * HH + l];
        float eB1 = two ? E[(TT - 3) * HH + 32 + l] : 0.0f;
        for (int t = TT - 2; t >= 0; t--) {
            float el0 = eA0, el1 = eA1;
            eA0 = eB0; eA1 = eB1;
            if (t - 2 >= 0) {
                eB0 = E[(t - 2) * HH + l];
                eB1 = two ? E[(t - 2) * HH + 32 + l] : 0.0f;
            }
            buf[t & 1][l] = el0 * b0;          // u_j = elep[t][j] * beta_{t+1}[j]
            if (two) buf[t & 1][32 + l] = el1 * b1;
            __syncwarp(FULL);
            const float4* v4 = (const float4*)buf[t & 1];
            float p0 = 0, p1 = 0, q0 = 0, q1 = 0;
#pragma unroll
            for (int j = 0; j < 12; j++) {
                float4 v = v4[j];
                p0 = fmaf(v.x, T0[4 * j + 0], p0); q0 = fmaf(v.x, T1[4 * j + 0], q0);
                p1 = fmaf(v.y, T0[4 * j + 1], p1); q1 = fmaf(v.y, T1[4 * j + 1], q1);
                p0 = fmaf(v.z, T0[4 * j + 2], p0); q0 = fmaf(v.z, T1[4 * j + 2], q0);
                p1 = fmaf(v.w, T0[4 * j + 3], p1); q1 = fmaf(v.w, T1[4 * j + 3], q1);
            }
            b0 = p0 + p1;
            b1 = q0 + q1;                       // stays 0 for l >= 16 (T1 = 0)
            g_beta[(size_t)(b * TT + t) * HH + l] = b0;
            if (two) g_beta[(size_t)(b * TT + t) * HH + 32 + l] = b1;
            if ((t & 1) == 0) {                 // underflow guard
                float s = b0 + b1;
#pragma unroll
                for (int o = 16; o > 0; o >>= 1) s += __shfl_xor_sync(FULL, s, o);
                float inv = 1.0f / s;
                b0 *= inv; b1 *= inv;
            }
        }
    }
}

// ---------------- kernel 4: per-(b,t) gamma / prior / xi terms ----------------
__global__ void __launch_bounds__(256) final_kernel(const int* __restrict__ seq) {
    __shared__ float lt[HH * HH];
    __shared__ float tp[HH * HH];
    __shared__ float sA[HH], sU[HH], sG[HH], sL[HH];
    __shared__ float red[32];
    int tid = threadIdx.x;
    int bt = blockIdx.x;
    int b = bt >> 9;
    int t = bt & (TT - 1);
    int len = seq[b];

    if (t >= len) {
        if (tid == 0) g_partial[bt] = 0.0f;
        return;
    }
    bool do_xi = (t >= 1);

    for (int i = tid; i < HH * HH; i += 256) {
        lt[i] = g_log_trans[i];
        tp[i] = g_trans_prob[i];
    }
    if (tid < HH) {
        int tb = (t + TT - len) & (TT - 1);
        float br = g_beta[(size_t)(b * TT + tb) * HH + tid];
        float at = g_alpha[(size_t)(b * TT + t) * HH + tid];
        float lpv = g_lep[(size_t)(b * TT + t) * HH + tid];
        float el = g_elep[(size_t)(b * TT + t) * HH + tid];
        sG[tid] = at * br;
        sU[tid] = el * br;
        sL[tid] = lpv;
        sA[tid] = (t > 0) ? g_alpha[(size_t)(b * TT + t - 1) * HH + tid] : 0.0f;
    }
    __syncthreads();

    float e = (tid < HH) ? sG[tid] : 0.0f;
    float Z = blockSum256(e, red);
    float E = blockSum256(e * ((tid < HH) ? sL[tid] : 0.0f), red);
    float total = E / Z;
    if (t == 0) {
        float P = blockSum256(e * ((tid < HH) ? g_lp[tid] : 0.0f), red);
        total += P / Z;
    }

    if (do_xi) {
        float z = 0.0f, w = 0.0f;
        for (int idx = tid; idx < HH * HH; idx += 256) {
            int i = idx / HH, j = idx - i * HH;
            float val = tp[idx] * sA[i] * sU[j];
            z += val;
            w = fmaf(val, lt[idx], w);
        }
        float Z2 = blockSum256(z, red);
        float W2 = blockSum256(w, red);
        total += W2 / Z2;
    }
    if (tid == 0) g_partial[bt] = total;
}

// ---------------- kernel 5: deterministic final reduction ----------------
__global__ void __launch_bounds__(256) reduce_kernel(float* __restrict__ out) {
    __shared__ float red[256];
    int tid = threadIdx.x;
    float s = 0.0f;
    for (int i = tid; i < MTOT; i += 256) s += g_partial[i];
    red[tid] = s;
    __syncthreads();
    for (int off = 128; off > 0; off >>= 1) {
        if (tid < off) red[tid] += red[tid + off];
        __syncthreads();
    }
    if (tid == 0) out[0] = red[0] * (1.0f / (float)BB);
}

// ---------------- launch ----------------
extern "C" void kernel_launch(void* const* d_in, const int* in_sizes, int n_in,
                              void* d_out, int out_size) {
    const float* emb  = (const float*)d_in[0];
    const float* obs  = (const float*)d_in[1];
    const float* sp   = (const float*)d_in[2];
    const float* ut   = (const float*)d_in[3];
    const float* ue   = (const float*)d_in[4];
    const float* Wm   = (const float*)d_in[5];
    const float* bias = (const float*)d_in[6];
    const int*   seq  = (const int*)d_in[7];
    float* out = (float*)d_out;

    cudaFuncSetAttribute(mma_fused_kernel, cudaFuncAttributeMaxDynamicSharedMemorySize, GEMM_SMEM);

    init_kernel<<<CONV_BLOCKS + 1, 256>>>(emb, Wm, sp, ut, ue);   // launch 1

    dim3 ggrid(NN / 96, MTOT / 128);
    mma_fused_kernel<<<ggrid, 256, GEMM_SMEM>>>(bias, obs);       // launch 2
    combine_kernel<<<(MTOT * HH + 255) / 256, 256>>>();           // launch 3

    scan_kernel<<<32, 32>>>();                                    // launch 4 <- ncu window
    final_kernel<<<MTOT, 256>>>(seq);                             // launch 5
    reduce_kernel<<<1, 256>>>(out);                               // launch 6
}